// round 2
// baseline (speedup 1.0000x reference)
#include <cuda_runtime.h>

// Problem: out[p, :] = cumsum(W, axis=1)[:, x[p]] + b, p in [0, 8192*200)
// x: int32 (8192*200), W: fp32 (64,129) row-major, b: fp32 (64), out: fp32 (8192*200*64)

#define F1 129                  // num_feature + 1
#define D  64                   // vector dim
#define NPOS (8192 * 200)       // 1,638,400 positions
#define TPB 256                 // threads per block
#define GROUPS_PER_BLOCK (TPB / 16)   // 16 positions per block-iter

// Precomputed lookup table: table[c*D + d] = b[d] + sum_{j<=c} W[d*F1 + j]
__device__ float g_table[F1 * D];

__global__ void build_table_kernel(const float* __restrict__ W,
                                   const float* __restrict__ b) {
    int d = threadIdx.x;          // 0..63, one output dim per thread
    if (d >= D) return;
    float s = b[d];
    const float* wrow = W + d * F1;
    #pragma unroll 1
    for (int c = 0; c < F1; ++c) {
        s += wrow[c];
        g_table[c * D + d] = s;   // transposed layout: column-of-x major
    }
}

__global__ void __launch_bounds__(TPB, 6)
embed_kernel(const int* __restrict__ x, float* __restrict__ out) {
    // Shared copy of the table, viewed as float4 rows: 129 rows * 16 float4
    __shared__ float4 tab[F1 * (D / 4)];   // 33,024 bytes

    const float4* gt = reinterpret_cast<const float4*>(g_table);
    #pragma unroll 1
    for (int i = threadIdx.x; i < F1 * (D / 4); i += TPB)
        tab[i] = gt[i];
    __syncthreads();

    const int lane16 = threadIdx.x & 15;        // which float4 within a row
    const int group  = threadIdx.x >> 4;        // 0..15, which position in block

    int p = blockIdx.x * GROUPS_PER_BLOCK + group;
    const int stride = gridDim.x * GROUPS_PER_BLOCK;

    #pragma unroll 1
    for (; p < NPOS; p += stride) {
        int xi = __ldg(&x[p]);                  // same address across the 16-lane group
        float4 v = tab[xi * (D / 4) + lane16];  // conflict-free: consecutive 16B/lane
        // streaming store: 16 lanes * 16B = 256B coalesced per position
        __stcs(reinterpret_cast<float4*>(out) + (size_t)p * (D / 4) + lane16, v);
    }
}

extern "C" void kernel_launch(void* const* d_in, const int* in_sizes, int n_in,
                              void* d_out, int out_size) {
    const int*   x = (const int*)  d_in[0];
    const float* W = (const float*)d_in[1];
    const float* b = (const float*)d_in[2];
    float*     out = (float*)d_out;

    build_table_kernel<<<1, 64>>>(W, b);

    // Persistent grid: 152 SMs * 6 CTAs (smem-limited: 33KB/CTA out of ~227KB)
    const int grid = 152 * 6;
    embed_kernel<<<grid, TPB>>>(x, out);
}